// round 10
// baseline (speedup 1.0000x reference)
#include <cuda_runtime.h>
#include <cuda_bf16.h>
#include <math.h>

// Shape (fixed): output [B=2, C=8, H=128, W=128, D=128] fp32.
// Slice = 128^3 elems = 524,288 float4 = 256 chunks of 2048 float4.
// Grid: 592 = 4*148 blocks (exactly 4 CTAs/SM, one balanced wave), 256 thr.
// 37 blocks per slice (16*37 = 592); block lb strides chunks lc = lb, lb+37, ...
// Chunk = 8 front-batched LDG.128 per thread (MLP_p1 = 8).
//
// Slice-local f4 = lc*2048 + u*256 + tid:
//   h = lc>>1                      (chunk constant -> FFMA via csum)
//   w = 64*(lc&1) + 8u + (tid>>5)  (chunk-const FFMA + immediate FFMA + hoisted)
//   d = 4*(tid&31) + lane-fraction (hoisted + t1+2t2+3t3)

#define NSLICE       16
#define BLK_PER_SL   37
#define NBLOCKS      (NSLICE * BLK_PER_SL)   // 592
#define THREADS      256
#define CHUNKS_PER_SL 256
#define CHUNK_F4     2048
#define SLICE_F4     524288

__device__ float4 g_partial[NBLOCKS];
__device__ unsigned int g_count = 0;

__device__ __constant__ int   c_ri[8] = {0, 1, 2, 3, 4, 5, 6, 0};
__device__ __constant__ int   c_rj[8] = {1, 2, 3, 4, 5, 6, 7, 7};
__device__ __constant__ float c_gy[8] = { 0.1f, 0.0f, -0.1f, 0.0f,  0.05f, 0.0f,  0.1f, -0.05f};
__device__ __constant__ float c_gx[8] = { 0.0f, 0.1f,  0.05f, 0.0f, -0.05f, 0.1f, 0.0f,  0.05f};
__device__ __constant__ float c_gz[8] = { 0.05f, 0.0f, 0.0f,  0.1f,  0.0f, -0.1f, 0.0f,  0.05f};

__global__ __launch_bounds__(THREADS, 4) void fused_kernel(const float* __restrict__ in,
                                                           float* __restrict__ out) {
    const int bc = blockIdx.x / BLK_PER_SL;       // slice 0..15
    const int lb = blockIdx.x % BLK_PER_SL;       // 0..36
    const int tid = threadIdx.x;

    const float4* __restrict__ p =
        reinterpret_cast<const float4*>(in) + (size_t)bc * SLICE_F4 + tid;

    float s = 0.f, sy = 0.f, sxl = 0.f, szf = 0.f;

    for (int lc = lb; lc < CHUNKS_PER_SL; lc += BLK_PER_SL) {
        const float4* __restrict__ q = p + (size_t)lc * CHUNK_F4;
        // 8 independent LDG.128 front-batched into named registers
        float4 v0 = q[0 * 256];
        float4 v1 = q[1 * 256];
        float4 v2 = q[2 * 256];
        float4 v3 = q[3 * 256];
        float4 v4 = q[4 * 256];
        float4 v5 = q[5 * 256];
        float4 v6 = q[6 * 256];
        float4 v7 = q[7 * 256];

        float csum = 0.f;
#pragma unroll
        for (int u = 0; u < 8; u++) {
            float4 v = (u == 0) ? v0 : (u == 1) ? v1 : (u == 2) ? v2 : (u == 3) ? v3
                     : (u == 4) ? v4 : (u == 5) ? v5 : (u == 6) ? v6 : v7;
            float t0 = v.x > 0.5f ? v.x : 0.f;
            float t1 = v.y > 0.5f ? v.y : 0.f;
            float t2 = v.z > 0.5f ? v.z : 0.f;
            float t3 = v.w > 0.5f ? v.w : 0.f;
            float tsum = (t0 + t1) + (t2 + t3);

            csum += tsum;
            sxl = fmaf(tsum, (float)(8 * u), sxl);   // immediate FFMA
            szf += t1;
            szf = fmaf(2.f, t2, szf);
            szf = fmaf(3.f, t3, szf);
        }
        sy  = fmaf((float)(lc >> 1), csum, sy);          // h = lc>>1
        sxl = fmaf((float)((lc & 1) << 6), csum, sxl);   // wbase = 64*(lc&1)
        s  += csum;
    }

    float sx = fmaf((float)(tid >> 5), s, sxl);
    float sz = fmaf((float)((tid & 31) << 2), s, szf);

    // warp reduction
    const unsigned FULL = 0xFFFFFFFFu;
#pragma unroll
    for (int off = 16; off > 0; off >>= 1) {
        s  += __shfl_down_sync(FULL, s,  off);
        sy += __shfl_down_sync(FULL, sy, off);
        sx += __shfl_down_sync(FULL, sx, off);
        sz += __shfl_down_sync(FULL, sz, off);
    }

    __shared__ float4 warp_acc[THREADS / 32];
    int lane = tid & 31;
    int wid  = tid >> 5;
    if (lane == 0) warp_acc[wid] = make_float4(s, sy, sx, sz);
    __syncthreads();

    if (wid == 0) {
        float4 a = (lane < THREADS / 32) ? warp_acc[lane] : make_float4(0.f, 0.f, 0.f, 0.f);
#pragma unroll
        for (int off = 4; off > 0; off >>= 1) {
            a.x += __shfl_down_sync(FULL, a.x, off);
            a.y += __shfl_down_sync(FULL, a.y, off);
            a.z += __shfl_down_sync(FULL, a.z, off);
            a.w += __shfl_down_sync(FULL, a.w, off);
        }
        if (lane == 0) g_partial[blockIdx.x] = a;
    }

    // ---- last-block finalize (threadfence reduction) ----
    __threadfence();
    __shared__ bool is_last;
    if (tid == 0) {
        unsigned old = atomicAdd(&g_count, 1u);
        is_last = (old == (unsigned)(NBLOCKS - 1));
        if (is_last) g_count = 0;            // reset for next graph replay
    }
    __syncthreads();
    if (!is_last) return;
    __threadfence();

    __shared__ float4 shp[NBLOCKS];          // ~9.5 KB
    __shared__ float  cent[NSLICE][3];
    for (int k = tid; k < NBLOCKS; k += THREADS) {
        const float4* gp = &g_partial[k];
        float4 a;
        a.x = __ldcg(&gp->x); a.y = __ldcg(&gp->y);
        a.z = __ldcg(&gp->z); a.w = __ldcg(&gp->w);
        shp[k] = a;
    }
    __syncthreads();

    if (tid < NSLICE) {
        float ss = 0.f, ssy = 0.f, ssx = 0.f, ssz = 0.f;
#pragma unroll
        for (int k = 0; k < BLK_PER_SL; k++) {
            float4 a = shp[tid * BLK_PER_SL + k];
            ss += a.x; ssy += a.y; ssx += a.z; ssz += a.w;
        }
        const float inv128 = 1.0f / 128.0f;
        float inv_s = 1.0f / ss;             // inf if ss==0; guarded below
        cent[tid][0] = ssy * inv_s * inv128;
        cent[tid][1] = ssx * inv_s * inv128;
        cent[tid][2] = ssz * inv_s * inv128;
    }
    __syncthreads();

    if (tid == 0) {
        float loss = 0.f;
#pragma unroll
        for (int r = 0; r < 8; r++) {
            int i = c_ri[r], j = c_rj[r];
            float acc = 0.f;
#pragma unroll
            for (int b = 0; b < 2; b++) {
                float dy = cent[b * 8 + i][0] - cent[b * 8 + j][0] - c_gy[r];
                float dx = cent[b * 8 + i][1] - cent[b * 8 + j][1] - c_gx[r];
                float dz = cent[b * 8 + i][2] - cent[b * 8 + j][2] - c_gz[r];
                if (!isfinite(dy)) dy = 0.f;
                if (!isfinite(dx)) dx = 0.f;
                if (!isfinite(dz)) dz = 0.f;
                acc += dy * dy + dx * dx + dz * dz;
            }
            loss += 0.5f * acc;              // mean over batch (B=2)
        }
        out[0] = loss;
    }
}

extern "C" void kernel_launch(void* const* d_in, const int* in_sizes, int n_in,
                              void* d_out, int out_size) {
    const float* in = (const float*)d_in[0];
    float* out = (float*)d_out;
    (void)in_sizes; (void)n_in; (void)out_size;

    fused_kernel<<<NBLOCKS, THREADS>>>(in, out);
}